// round 1
// baseline (speedup 1.0000x reference)
#include <cuda_runtime.h>
#include <cuda_bf16.h>

#define NN 4096
#define DD 512
#define BM 128
#define BN 128
#define BK 16
#define MARGIN_F 0.3f

// Scratch (allocation-free rule: __device__ globals)
__device__ float    g_e1[NN];
__device__ float    g_e2[NN];
__device__ unsigned g_ap[NN];   // bits of non-negative float, atomicMax-able
__device__ unsigned g_an[NN];   // bits of non-negative float, atomicMin-able
__device__ int      g_lab[NN];

// ---------------------------------------------------------------------------
// prep: per-row squared norms of src and tgt + init ap/an accumulators
// ---------------------------------------------------------------------------
__global__ void prep_kernel(const float* __restrict__ src,
                            const float* __restrict__ tgt) {
    int row = blockIdx.x;
    int t = threadIdx.x;  // 128 threads
    const float* s = src + (size_t)row * DD;
    const float* g = tgt + (size_t)row * DD;
    float a = 0.f, b = 0.f;
    for (int i = t; i < DD; i += 128) {
        float x = s[i]; a = fmaf(x, x, a);
        float y = g[i]; b = fmaf(y, y, b);
    }
#pragma unroll
    for (int o = 16; o > 0; o >>= 1) {
        a += __shfl_xor_sync(0xffffffffu, a, o);
        b += __shfl_xor_sync(0xffffffffu, b, o);
    }
    __shared__ float sa[4], sb[4];
    int w = t >> 5;
    if ((t & 31) == 0) { sa[w] = a; sb[w] = b; }
    __syncthreads();
    if (t == 0) {
        g_e1[row] = sa[0] + sa[1] + sa[2] + sa[3];
        g_e2[row] = sb[0] + sb[1] + sb[2] + sb[3];
        g_ap[row] = 0u;           // dist >= 0, max-accumulator
        g_an[row] = 0x7f800000u;  // +inf, min-accumulator
    }
}

// ---------------------------------------------------------------------------
// label_norm: detect int64 vs int32 labels and normalize to g_lab[] (int)
// int64 little-endian: odd int32 words (high words) are all zero.
// ---------------------------------------------------------------------------
__global__ void label_norm_kernel(const int* __restrict__ lab32) {
    __shared__ int any_odd_nonzero;
    int t = threadIdx.x;  // 1024 threads, single block
    if (t == 0) any_odd_nonzero = 0;
    __syncthreads();
    int local = 0;
    // scan odd indices among the first 4096 int32 words (safe for both dtypes)
    for (int i = 2 * t + 1; i < NN; i += 2 * 1024) {
        if (lab32[i] != 0) local = 1;
    }
    if (local) atomicOr(&any_odd_nonzero, 1);
    __syncthreads();
    bool is64 = (any_odd_nonzero == 0);
    for (int i = t; i < NN; i += 1024) {
        g_lab[i] = is64 ? lab32[2 * i] : lab32[i];
    }
}

// ---------------------------------------------------------------------------
// dist: 128x128 tile of dist = e1 + e2 - 2*S*T^T over K=512, fused
// label-masked row max (ap) / min (an) epilogue.
// 256 threads, 8x8 microtile per thread (rows split 4+4, cols split 4+4).
// ---------------------------------------------------------------------------
__global__ void __launch_bounds__(256) dist_kernel(
    const float* __restrict__ src, const float* __restrict__ tgt) {
    __shared__ float As[BK][BM];
    __shared__ float Bs[BK][BN];
    __shared__ float sE1[BM], sE2[BN];
    __shared__ int   sLr[BM], sLc[BN];
    __shared__ unsigned sAp[BM], sAn[BM];

    const int rowBase = blockIdx.y * BM;
    const int colBase = blockIdx.x * BN;
    const int tid = threadIdx.x;
    const int tr = tid >> 4;   // 0..15
    const int tc = tid & 15;   // 0..15

    if (tid < 128) {
        sAp[tid] = 0u;
        sAn[tid] = 0x7f800000u;
        sE1[tid] = g_e1[rowBase + tid];
        sE2[tid] = g_e2[colBase + tid];
        sLr[tid] = g_lab[rowBase + tid];
        sLc[tid] = g_lab[colBase + tid];
    }

    float acc[8][8];
#pragma unroll
    for (int i = 0; i < 8; i++)
#pragma unroll
        for (int j = 0; j < 8; j++) acc[i][j] = 0.f;

    for (int kt = 0; kt < DD; kt += BK) {
        // Load A tile [BM x BK] and B tile [BN x BK], store K-major transposed.
#pragma unroll
        for (int l = 0; l < 2; l++) {
            int f  = tid * 2 + l;   // 0..511 float4 slots (128 rows x 4)
            int r  = f >> 2;
            int c4 = (f & 3) * 4;
            float4 va = *(const float4*)(src + (size_t)(rowBase + r) * DD + kt + c4);
            As[c4 + 0][r] = va.x; As[c4 + 1][r] = va.y;
            As[c4 + 2][r] = va.z; As[c4 + 3][r] = va.w;
            float4 vb = *(const float4*)(tgt + (size_t)(colBase + r) * DD + kt + c4);
            Bs[c4 + 0][r] = vb.x; Bs[c4 + 1][r] = vb.y;
            Bs[c4 + 2][r] = vb.z; Bs[c4 + 3][r] = vb.w;
        }
        __syncthreads();
#pragma unroll
        for (int k = 0; k < BK; k++) {
            float4 a0 = *(const float4*)&As[k][tr * 4];
            float4 a1 = *(const float4*)&As[k][64 + tr * 4];
            float4 b0 = *(const float4*)&Bs[k][tc * 4];
            float4 b1 = *(const float4*)&Bs[k][64 + tc * 4];
            float a[8] = {a0.x, a0.y, a0.z, a0.w, a1.x, a1.y, a1.z, a1.w};
            float b[8] = {b0.x, b0.y, b0.z, b0.w, b1.x, b1.y, b1.z, b1.w};
#pragma unroll
            for (int i = 0; i < 8; i++)
#pragma unroll
                for (int j = 0; j < 8; j++)
                    acc[i][j] = fmaf(a[i], b[j], acc[i][j]);
        }
        __syncthreads();
    }

    // Fused epilogue: dist -> clamp -> label mask -> per-row max/min
#pragma unroll
    for (int i = 0; i < 8; i++) {
        int r = (i < 4) ? (tr * 4 + i) : (64 + tr * 4 + i - 4);
        float e1v = sE1[r];
        int   lr  = sLr[r];
        float apv = 0.f;
        float anv = __int_as_float(0x7f800000);
#pragma unroll
        for (int j = 0; j < 8; j++) {
            int c = (j < 4) ? (tc * 4 + j) : (64 + tc * 4 + j - 4);
            float d = fmaf(-2.f, acc[i][j], e1v + sE2[c]);
            d = fmaxf(d, 0.f);
            if (lr == sLc[c]) apv = fmaxf(apv, d);
            else              anv = fminf(anv, d);
        }
        atomicMax(&sAp[r], __float_as_uint(apv));
        atomicMin(&sAn[r], __float_as_uint(anv));
    }
    __syncthreads();
    if (tid < 128) {
        atomicMax(&g_ap[rowBase + tid], sAp[tid]);
        atomicMin(&g_an[rowBase + tid], sAn[tid]);
    }
}

// ---------------------------------------------------------------------------
// reduce: deterministic single-block mean of relu(ap - an + margin)
// ---------------------------------------------------------------------------
__global__ void reduce_kernel(float* __restrict__ out) {
    __shared__ float sbuf[1024];
    int t = threadIdx.x;
    float s = 0.f;
    for (int i = t; i < NN; i += 1024) {
        float ap = __uint_as_float(g_ap[i]);
        float an = __uint_as_float(g_an[i]);
        s += fmaxf(ap - an + MARGIN_F, 0.f);
    }
    sbuf[t] = s;
    __syncthreads();
#pragma unroll
    for (int o = 512; o > 0; o >>= 1) {
        if (t < o) sbuf[t] += sbuf[t + o];
        __syncthreads();
    }
    if (t == 0) out[0] = sbuf[0] * (1.0f / (float)NN);
}

// ---------------------------------------------------------------------------
extern "C" void kernel_launch(void* const* d_in, const int* in_sizes, int n_in,
                              void* d_out, int out_size) {
    const float* src = (const float*)d_in[0];
    const float* tgt = (const float*)d_in[1];
    const int*   lab = (const int*)d_in[2];  // int32 view; dtype detected on device

    prep_kernel<<<NN, 128>>>(src, tgt);
    label_norm_kernel<<<1, 1024>>>(lab);
    dist_kernel<<<dim3(NN / BN, NN / BM), 256>>>(src, tgt);
    reduce_kernel<<<1, 1024>>>((float*)d_out);
}

// round 3
// speedup vs baseline: 3.9288x; 3.9288x over previous
#include <cuda_runtime.h>
#include <cuda_bf16.h>
#include <cstdint>

#define NN 4096
#define DD 512
#define BM 128
#define BN 128
#define KC 32                    // K elems per chunk = 128B per row
#define NCHUNK (DD / KC)         // 16
#define MARGIN_F 0.3f

#define TILE_BYTES (BM * 128)    // 16 KB per operand per stage
#define A_OFF(s) ((s) * TILE_BYTES)
#define B_OFF(s) (2 * TILE_BYTES + (s) * TILE_BYTES)
#define DYN_SMEM (4 * TILE_BYTES)   // 64 KB

__device__ float    g_e1[NN];
__device__ float    g_e2[NN];
__device__ unsigned g_ap[NN];   // non-negative float bits, atomicMax
__device__ unsigned g_an[NN];   // non-negative float bits, atomicMin
__device__ int      g_lab[NN];

// ---------------------------------------------------------------------------
__device__ __forceinline__ void cp_async16(void* dst, const void* src) {
    uint32_t d;
    asm("{ .reg .u64 t; cvta.to.shared.u64 t, %1; cvt.u32.u64 %0, t; }"
        : "=r"(d) : "l"(dst));
    asm volatile("cp.async.cg.shared.global [%0], [%1], 16;" :: "r"(d), "l"(src));
}
__device__ __forceinline__ void mma_tf32(float* d, const uint32_t* a,
                                         uint32_t b0, uint32_t b1) {
    asm volatile(
        "mma.sync.aligned.m16n8k8.row.col.f32.tf32.tf32.f32 "
        "{%0,%1,%2,%3}, {%4,%5,%6,%7}, {%8,%9}, {%0,%1,%2,%3};"
        : "+f"(d[0]), "+f"(d[1]), "+f"(d[2]), "+f"(d[3])
        : "r"(a[0]), "r"(a[1]), "r"(a[2]), "r"(a[3]), "r"(b0), "r"(b1));
}
// SW128-swizzled tile element: tile row-major [row][128B], 16B chunk XOR row%8
__device__ __forceinline__ uint32_t tile_ld(const char* base, int row,
                                            int chunk16, int t4) {
    return *(const uint32_t*)(base + row * 128 + ((chunk16 ^ (row & 7)) << 4) + t4 * 4);
}

// ---------------------------------------------------------------------------
// prep: per-row squared norms + accumulator init
// ---------------------------------------------------------------------------
__global__ void prep_kernel(const float* __restrict__ src,
                            const float* __restrict__ tgt) {
    int row = blockIdx.x;
    int t = threadIdx.x;  // 128
    const float* s = src + (size_t)row * DD;
    const float* g = tgt + (size_t)row * DD;
    float a = 0.f, b = 0.f;
    for (int i = t; i < DD; i += 128) {
        float x = s[i]; a = fmaf(x, x, a);
        float y = g[i]; b = fmaf(y, y, b);
    }
#pragma unroll
    for (int o = 16; o > 0; o >>= 1) {
        a += __shfl_xor_sync(0xffffffffu, a, o);
        b += __shfl_xor_sync(0xffffffffu, b, o);
    }
    __shared__ float sa[4], sb[4];
    int w = t >> 5;
    if ((t & 31) == 0) { sa[w] = a; sb[w] = b; }
    __syncthreads();
    if (t == 0) {
        g_e1[row] = sa[0] + sa[1] + sa[2] + sa[3];
        g_e2[row] = sb[0] + sb[1] + sb[2] + sb[3];
        g_ap[row] = 0u;
        g_an[row] = 0x7f800000u;
    }
}

// ---------------------------------------------------------------------------
// label_norm: int64-vs-int32 detection + normalize to int
// ---------------------------------------------------------------------------
__global__ void label_norm_kernel(const int* __restrict__ lab32) {
    __shared__ int any_odd_nonzero;
    int t = threadIdx.x;  // 1024
    if (t == 0) any_odd_nonzero = 0;
    __syncthreads();
    int local = 0;
    for (int i = 2 * t + 1; i < NN; i += 2 * 1024)
        if (lab32[i] != 0) local = 1;
    if (local) atomicOr(&any_odd_nonzero, 1);
    __syncthreads();
    bool is64 = (any_odd_nonzero == 0);
    for (int i = t; i < NN; i += 1024)
        g_lab[i] = is64 ? lab32[2 * i] : lab32[i];
}

// ---------------------------------------------------------------------------
// dist_mma: 128x128 tile via mma.sync tf32, 2-stage cp.async double buffer,
// fused label-masked row max/min epilogue.
// 8 warps: 4 (M) x 2 (N); warp tile 32x64; frags m16n8k8.
// ---------------------------------------------------------------------------
__global__ void __launch_bounds__(256, 2) dist_mma_kernel(
    const float* __restrict__ src, const float* __restrict__ tgt) {
    extern __shared__ char smem[];
    __shared__ float sE1[BM], sE2[BN];
    __shared__ int   sLr[BM], sLc[BN];
    __shared__ unsigned sAp[BM], sAn[BM];

    const int tid = threadIdx.x;
    const int wid = tid >> 5;
    const int lid = tid & 31;
    const int gid = lid >> 2;     // group 0..7
    const int t4  = lid & 3;      // 0..3
    const int warpM = wid & 3;    // 0..3 -> 32-row slab
    const int warpN = wid >> 2;   // 0..1 -> 64-col slab
    const int rowBase = blockIdx.y * BM;
    const int colBase = blockIdx.x * BN;

    if (tid < 128) {
        sAp[tid] = 0u;
        sAn[tid] = 0x7f800000u;
        sE1[tid] = g_e1[rowBase + tid];
        sE2[tid] = g_e2[colBase + tid];
        sLr[tid] = g_lab[rowBase + tid];
        sLc[tid] = g_lab[colBase + tid];
    }

    // chunk loader: 128 rows x 128B, SW128 swizzle; 1024 16B slots / 256 thr
    auto load_chunk = [&](const float* __restrict__ base, int rb, int kt, char* dst) {
#pragma unroll
        for (int i = 0; i < 4; i++) {
            int f = tid + i * 256;
            int r = f >> 3;
            int c16 = f & 7;
            const float* g = base + (size_t)(rb + r) * DD + kt + c16 * 4;
            cp_async16(dst + r * 128 + ((c16 ^ (r & 7)) << 4), g);
        }
    };

    float acc[2][8][4];
#pragma unroll
    for (int mf = 0; mf < 2; mf++)
#pragma unroll
        for (int nf = 0; nf < 8; nf++)
#pragma unroll
            for (int v = 0; v < 4; v++) acc[mf][nf][v] = 0.f;

    load_chunk(src, rowBase, 0, smem + A_OFF(0));
    load_chunk(tgt, colBase, 0, smem + B_OFF(0));
    asm volatile("cp.async.commit_group;");

    for (int c = 0; c < NCHUNK; c++) {
        int s = c & 1;
        if (c + 1 < NCHUNK) {
            int sn = (c + 1) & 1;
            load_chunk(src, rowBase, (c + 1) * KC, smem + A_OFF(sn));
            load_chunk(tgt, colBase, (c + 1) * KC, smem + B_OFF(sn));
            asm volatile("cp.async.commit_group;");
            asm volatile("cp.async.wait_group 1;");
        } else {
            asm volatile("cp.async.wait_group 0;");
        }
        __syncthreads();

        const char* As = smem + A_OFF(s);
        const char* Bs = smem + B_OFF(s);
#pragma unroll
        for (int ks = 0; ks < 4; ks++) {     // 4 x K=8
            uint32_t a[2][4];
#pragma unroll
            for (int mf = 0; mf < 2; mf++) {
                int r0 = warpM * 32 + mf * 16 + gid;
                a[mf][0] = tile_ld(As, r0,     ks * 2,     t4);
                a[mf][1] = tile_ld(As, r0 + 8, ks * 2,     t4);
                a[mf][2] = tile_ld(As, r0,     ks * 2 + 1, t4);
                a[mf][3] = tile_ld(As, r0 + 8, ks * 2 + 1, t4);
            }
#pragma unroll
            for (int nf = 0; nf < 8; nf++) {
                int col = warpN * 64 + nf * 8 + gid;
                uint32_t b0 = tile_ld(Bs, col, ks * 2,     t4);
                uint32_t b1 = tile_ld(Bs, col, ks * 2 + 1, t4);
                mma_tf32(acc[0][nf], a[0], b0, b1);
                mma_tf32(acc[1][nf], a[1], b0, b1);
            }
        }
        __syncthreads();
    }

    // ---- epilogue: dist -> clamp -> mask -> row max/min ----
#pragma unroll
    for (int mf = 0; mf < 2; mf++) {
#pragma unroll
        for (int half = 0; half < 2; half++) {
            int row = warpM * 32 + mf * 16 + half * 8 + gid;
            float e1v = sE1[row];
            int   lr  = sLr[row];
            float apv = 0.f;
            float anv = __int_as_float(0x7f800000);
#pragma unroll
            for (int nf = 0; nf < 8; nf++) {
                int c0 = warpN * 64 + nf * 8 + t4 * 2;
#pragma unroll
                for (int v = 0; v < 2; v++) {
                    int col = c0 + v;
                    float d = fmaf(-2.f, acc[mf][nf][half * 2 + v], e1v + sE2[col]);
                    d = fmaxf(d, 0.f);
                    if (lr == sLc[col]) apv = fmaxf(apv, d);
                    else                anv = fminf(anv, d);
                }
            }
            // reduce over the 4 lanes of the quad (disjoint col sets, same row)
#pragma unroll
            for (int o = 1; o <= 2; o <<= 1) {
                apv = fmaxf(apv, __shfl_xor_sync(0xffffffffu, apv, o));
                anv = fminf(anv, __shfl_xor_sync(0xffffffffu, anv, o));
            }
            if (t4 == 0) {
                atomicMax(&sAp[row], __float_as_uint(apv));
                atomicMin(&sAn[row], __float_as_uint(anv));
            }
        }
    }
    __syncthreads();
    if (tid < 128) {
        atomicMax(&g_ap[rowBase + tid], sAp[tid]);
        atomicMin(&g_an[rowBase + tid], sAn[tid]);
    }
}

// ---------------------------------------------------------------------------
// reduce: deterministic single-block mean of relu(ap - an + margin)
// ---------------------------------------------------------------------------
__global__ void reduce_kernel(float* __restrict__ out) {
    __shared__ float sw[32];
    int t = threadIdx.x;  // 1024
    float s = 0.f;
#pragma unroll
    for (int i = t; i < NN; i += 1024) {
        float ap = __uint_as_float(g_ap[i]);
        float an = __uint_as_float(g_an[i]);
        s += fmaxf(ap - an + MARGIN_F, 0.f);
    }
#pragma unroll
    for (int o = 16; o > 0; o >>= 1) s += __shfl_xor_sync(0xffffffffu, s, o);
    if ((t & 31) == 0) sw[t >> 5] = s;
    __syncthreads();
    if (t < 32) {
        float v = sw[t];
#pragma unroll
        for (int o = 16; o > 0; o >>= 1) v += __shfl_xor_sync(0xffffffffu, v, o);
        if (t == 0) out[0] = v * (1.0f / (float)NN);
    }
}

// ---------------------------------------------------------------------------
extern "C" void kernel_launch(void* const* d_in, const int* in_sizes, int n_in,
                              void* d_out, int out_size) {
    const float* src = (const float*)d_in[0];
    const float* tgt = (const float*)d_in[1];
    const int*   lab = (const int*)d_in[2];

    cudaFuncSetAttribute(dist_mma_kernel,
                         cudaFuncAttributeMaxDynamicSharedMemorySize, DYN_SMEM);

    prep_kernel<<<NN, 128>>>(src, tgt);
    label_norm_kernel<<<1, 1024>>>(lab);
    dist_mma_kernel<<<dim3(NN / BN, NN / BM), 256, DYN_SMEM>>>(src, tgt);
    reduce_kernel<<<1, 1024>>>((float*)d_out);
}

// round 7
// speedup vs baseline: 7.1954x; 1.8314x over previous
#include <cuda_runtime.h>
#include <cuda_fp16.h>
#include <cstdint>

#define NN 4096
#define DD 512
#define BM 128
#define BN 128
#define KC 64                    // fp16 K elems per chunk = 128B per row
#define NCHUNK (DD / KC)         // 8
#define MARGIN_F 0.3f

#define TILE_BYTES (BM * 128)    // 16 KB per operand per stage
#define A_OFF(s) ((s) * TILE_BYTES)
#define B_OFF(s) (2 * TILE_BYTES + (s) * TILE_BYTES)
#define DYN_SMEM (4 * TILE_BYTES)   // 64 KB

__device__ float    g_e1[NN];
__device__ float    g_e2[NN];
__device__ unsigned g_ap[NN];      // non-negative float bits, atomicMax
__device__ unsigned g_an[NN];      // non-negative float bits, atomicMin
__device__ int      g_lab[NN];
__device__ __half   g_srch[NN * DD];   // fp16 copies (4 MB each)
__device__ __half   g_tgth[NN * DD];

// ---------------------------------------------------------------------------
__device__ __forceinline__ uint32_t h2_bits(__half2 h) {
    return *reinterpret_cast<uint32_t*>(&h);
}
__device__ __forceinline__ uint32_t smem_u32(const void* p) {
    uint32_t a;
    asm("{ .reg .u64 t; cvta.to.shared.u64 t, %1; cvt.u32.u64 %0, t; }"
        : "=r"(a) : "l"(p));
    return a;
}
__device__ __forceinline__ void cp_async16(uint32_t dst, const void* src) {
    asm volatile("cp.async.cg.shared.global [%0], [%1], 16;" :: "r"(dst), "l"(src));
}
__device__ __forceinline__ void ldsm_x4(uint32_t addr, uint32_t& r0, uint32_t& r1,
                                        uint32_t& r2, uint32_t& r3) {
    asm volatile("ldmatrix.sync.aligned.m8n8.x4.shared.b16 {%0,%1,%2,%3}, [%4];"
                 : "=r"(r0), "=r"(r1), "=r"(r2), "=r"(r3) : "r"(addr));
}
__device__ __forceinline__ void mma_f16(float* d, uint32_t a0, uint32_t a1,
                                        uint32_t a2, uint32_t a3,
                                        uint32_t b0, uint32_t b1) {
    asm volatile(
        "mma.sync.aligned.m16n8k16.row.col.f32.f16.f16.f32 "
        "{%0,%1,%2,%3}, {%4,%5,%6,%7}, {%8,%9}, {%0,%1,%2,%3};"
        : "+f"(d[0]), "+f"(d[1]), "+f"(d[2]), "+f"(d[3])
        : "r"(a0), "r"(a1), "r"(a2), "r"(a3), "r"(b0), "r"(b1));
}

// ---------------------------------------------------------------------------
// prep: fp32->fp16 convert + per-row squared norms (fp32) + accumulator init
// ---------------------------------------------------------------------------
__global__ void prep_kernel(const float* __restrict__ src,
                            const float* __restrict__ tgt) {
    int row = blockIdx.x;
    int t = threadIdx.x;  // 128
    const float4* s4 = (const float4*)(src + (size_t)row * DD);
    const float4* g4 = (const float4*)(tgt + (size_t)row * DD);
    uint2* sh = (uint2*)(g_srch + (size_t)row * DD);
    uint2* gh = (uint2*)(g_tgth + (size_t)row * DD);
    float a = 0.f, b = 0.f;
    {
        float4 x = s4[t];
        a = x.x*x.x + x.y*x.y + x.z*x.z + x.w*x.w;
        uint2 o;
        o.x = h2_bits(__floats2half2_rn(x.x, x.y));
        o.y = h2_bits(__floats2half2_rn(x.z, x.w));
        sh[t] = o;
        float4 y = g4[t];
        b = y.x*y.x + y.y*y.y + y.z*y.z + y.w*y.w;
        o.x = h2_bits(__floats2half2_rn(y.x, y.y));
        o.y = h2_bits(__floats2half2_rn(y.z, y.w));
        gh[t] = o;
    }
#pragma unroll
    for (int o = 16; o > 0; o >>= 1) {
        a += __shfl_xor_sync(0xffffffffu, a, o);
        b += __shfl_xor_sync(0xffffffffu, b, o);
    }
    __shared__ float sa[4], sb[4];
    int w = t >> 5;
    if ((t & 31) == 0) { sa[w] = a; sb[w] = b; }
    __syncthreads();
    if (t == 0) {
        g_e1[row] = sa[0] + sa[1] + sa[2] + sa[3];
        g_e2[row] = sb[0] + sb[1] + sb[2] + sb[3];
        g_ap[row] = 0u;
        g_an[row] = 0x7f800000u;
    }
}

// ---------------------------------------------------------------------------
// label_norm: int64-vs-int32 detection + normalize to int
// ---------------------------------------------------------------------------
__global__ void label_norm_kernel(const int* __restrict__ lab32) {
    __shared__ int any_odd_nonzero;
    int t = threadIdx.x;  // 1024
    if (t == 0) any_odd_nonzero = 0;
    __syncthreads();
    int local = 0;
    for (int i = 2 * t + 1; i < NN; i += 2 * 1024)
        if (lab32[i] != 0) local = 1;
    if (local) atomicOr(&any_odd_nonzero, 1);
    __syncthreads();
    bool is64 = (any_odd_nonzero == 0);
    for (int i = t; i < NN; i += 1024)
        g_lab[i] = is64 ? lab32[2 * i] : lab32[i];
}

// ---------------------------------------------------------------------------
// dist_mma: 128x128 tile via mma.sync fp16 m16n8k16, ldmatrix fragment feed,
// 2-stage cp.async double buffer, fused label-masked row max/min epilogue.
// 8 warps: 4 (M) x 2 (N); warp tile 32x64.
// ---------------------------------------------------------------------------
__global__ void __launch_bounds__(256, 2) dist_mma_kernel() {
    extern __shared__ char smem[];
    __shared__ float sE1[BM], sE2[BN];
    __shared__ int   sLr[BM], sLc[BN];
    __shared__ unsigned sAp[BM], sAn[BM];

    const int tid = threadIdx.x;
    const int wid = tid >> 5;
    const int lid = tid & 31;
    const int gid = lid >> 2;
    const int t4  = lid & 3;
    const int warpM = wid & 3;
    const int warpN = wid >> 2;
    const int rowBase = blockIdx.y * BM;
    const int colBase = blockIdx.x * BN;

    if (tid < 128) {
        sAp[tid] = 0u;
        sAn[tid] = 0x7f800000u;
        sE1[tid] = g_e1[rowBase + tid];
        sE2[tid] = g_e2[colBase + tid];
        sLr[tid] = g_lab[rowBase + tid];
        sLc[tid] = g_lab[colBase + tid];
    }

    const uint32_t sbase = smem_u32(smem);
    // per-lane ldmatrix invariants
    const int l7 = lid & 7;
    // A: frag f=lid/8: row = warpM*32 + mf*16 + (f&1)*8 + l7 ; c16 += f>>1
    uint32_t aRow[2];
#pragma unroll
    for (int mf = 0; mf < 2; mf++)
        aRow[mf] = (uint32_t)((warpM * 32 + mf * 16 + ((lid >> 3) & 1) * 8 + l7) * 128);
    const int aSel = lid >> 4;          // add to c16
    // B: pair p: col = warpN*64 + p*16 + (f>>1)*8 + l7 ; c16 += f&1
    uint32_t bCol[4];
#pragma unroll
    for (int p = 0; p < 4; p++)
        bCol[p] = (uint32_t)((warpN * 64 + p * 16 + (lid >> 4) * 8 + l7) * 128);
    const int bSel = (lid >> 3) & 1;

    // chunk loader: 128 rows x 128B (= 64 fp16), SW128 swizzle
    auto load_chunk = [&](const __half* __restrict__ base, int rb, int kt, uint32_t dst) {
#pragma unroll
        for (int i = 0; i < 4; i++) {
            int f = tid + i * 256;      // 0..1023 16B slots
            int r = f >> 3;
            int c16 = f & 7;
            const __half* g = base + (size_t)(rb + r) * DD + kt + c16 * 8;
            cp_async16(dst + r * 128 + ((c16 ^ (r & 7)) << 4), g);
        }
    };

    float acc[2][8][4];
#pragma unroll
    for (int mf = 0; mf < 2; mf++)
#pragma unroll
        for (int nf = 0; nf < 8; nf++)
#pragma unroll
            for (int v = 0; v < 4; v++) acc[mf][nf][v] = 0.f;

    load_chunk(g_srch, rowBase, 0, sbase + A_OFF(0));
    load_chunk(g_tgth, colBase, 0, sbase + B_OFF(0));
    asm volatile("cp.async.commit_group;");

    for (int c = 0; c < NCHUNK; c++) {
        int st = c & 1;
        if (c + 1 < NCHUNK) {
            int sn = (c + 1) & 1;
            load_chunk(g_srch, rowBase, (c + 1) * KC, sbase + A_OFF(sn));
            load_chunk(g_tgth, colBase, (c + 1) * KC, sbase + B_OFF(sn));
            asm volatile("cp.async.commit_group;");
            asm volatile("cp.async.wait_group 1;");
        } else {
            asm volatile("cp.async.wait_group 0;");
        }
        __syncthreads();

        const uint32_t Ab = sbase + A_OFF(st);
        const uint32_t Bb = sbase + B_OFF(st);
#pragma unroll
        for (int s = 0; s < 4; s++) {          // 4 x K=16
            uint32_t a[2][4];
#pragma unroll
            for (int mf = 0; mf < 2; mf++) {
                uint32_t addr = Ab + aRow[mf] + ((uint32_t)((s * 2 + aSel) ^ l7) << 4);
                ldsm_x4(addr, a[mf][0], a[mf][1], a[mf][2], a[mf][3]);
            }
#pragma unroll
            for (int p = 0; p < 4; p++) {
                uint32_t b0a, b1a, b0b, b1b;
                uint32_t addr = Bb + bCol[p] + ((uint32_t)((s * 2 + bSel) ^ l7) << 4);
                ldsm_x4(addr, b0a, b1a, b0b, b1b);
                mma_f16(acc[0][2 * p],     a[0][0], a[0][1], a[0][2], a[0][3], b0a, b1a);
                mma_f16(acc[1][2 * p],     a[1][0], a[1][1], a[1][2], a[1][3], b0a, b1a);
                mma_f16(acc[0][2 * p + 1], a[0][0], a[0][1], a[0][2], a[0][3], b0b, b1b);
                mma_f16(acc[1][2 * p + 1], a[1][0], a[1][1], a[1][2], a[1][3], b0b, b1b);
            }
        }
        __syncthreads();
    }

    // ---- epilogue: dist -> clamp -> mask -> row max/min ----
#pragma unroll
    for (int mf = 0; mf < 2; mf++) {
#pragma unroll
        for (int half = 0; half < 2; half++) {
            int row = warpM * 32 + mf * 16 + half * 8 + gid;
            float e1v = sE1[row];
            int   lr  = sLr[row];
            float apv = 0.f;
            float anv = __int_as_float(0x7f800000);
#pragma unroll
            for (int nf = 0; nf < 8; nf++) {
                int c0 = warpN * 64 + nf * 8 + t4 * 2;
#pragma unroll
                for (int v = 0; v < 2; v++) {
                    int col = c0 + v;
                    float d = fmaf(-2.f, acc[mf][nf][half * 2 + v], e1v + sE2[col]);
                    d = fmaxf(d, 0.f);
                    if (lr == sLc[col]) apv = fmaxf(apv, d);
                    else                anv = fminf(anv, d);
                }
            }
#pragma unroll
            for (int o = 1; o <= 2; o <<= 1) {
                apv = fmaxf(apv, __shfl_xor_sync(0xffffffffu, apv, o));
                anv = fminf(anv, __shfl_xor_sync(0xffffffffu, anv, o));
            }
            if (t4 == 0) {
                atomicMax(&sAp[row], __float_as_uint(apv));
                atomicMin(&sAn[row], __float_as_uint(anv));
            }
        }
    }
    __syncthreads();
    if (tid < 128) {
        atomicMax(&g_ap[rowBase + tid], sAp[tid]);
        atomicMin(&g_an[rowBase + tid], sAn[tid]);
    }
}

// ---------------------------------------------------------------------------
// reduce: deterministic single-block mean of relu(ap - an + margin)
// ---------------------------------------------------------------------------
__global__ void reduce_kernel(float* __restrict__ out) {
    __shared__ float sw[32];
    int t = threadIdx.x;  // 1024
    float s = 0.f;
#pragma unroll
    for (int i = t; i < NN; i += 1024) {
        float ap = __uint_as_float(g_ap[i]);
        float an = __uint_as_float(g_an[i]);
        s += fmaxf(ap - an + MARGIN_F, 0.f);
    }
#pragma unroll
    for (int o = 16; o > 0; o >>= 1) s += __shfl_xor_sync(0xffffffffu, s, o);
    if ((t & 31) == 0) sw[t >> 5] = s;
    __syncthreads();
    if (t < 32) {
        float v = sw[t];
#pragma unroll
        for (int o = 16; o > 0; o >>= 1) v += __shfl_xor_sync(0xffffffffu, v, o);
        if (t == 0) out[0] = v * (1.0f / (float)NN);
    }
}

// ---------------------------------------------------------------------------
extern "C" void kernel_launch(void* const* d_in, const int* in_sizes, int n_in,
                              void* d_out, int out_size) {
    const float* src = (const float*)d_in[0];
    const float* tgt = (const float*)d_in[1];
    const int*   lab = (const int*)d_in[2];

    cudaFuncSetAttribute(dist_mma_kernel,
                         cudaFuncAttributeMaxDynamicSharedMemorySize, DYN_SMEM);

    prep_kernel<<<NN, 128>>>(src, tgt);
    label_norm_kernel<<<1, 1024>>>(lab);
    dist_mma_kernel<<<dim3(NN / BN, NN / BM), 256, DYN_SMEM>>>();
    reduce_kernel<<<1, 1024>>>((float*)d_out);
}